// round 5
// baseline (speedup 1.0000x reference)
#include <cuda_runtime.h>

// Problem constants (from reference setup_inputs)
#define BD   8        // batch
#define NN   2048     // N = O*K
#define HH   128      // hidden
#define TT   10       // pred_len
#define MAXN 256      // neighbor cap (avg degree ~10)

// ---------------- device scratch (no allocations allowed) ----------------
__device__ float g_pos[BD * NN * 3];
__device__ float g_vel[BD * NN * 3];
__device__ float g_xa[BD * NN * HH];
__device__ float g_xb[BD * NN * HH];
__device__ float g_h [BD * NN * HH];
__device__ int   g_nbr[BD * NN * MAXN];
__device__ int   g_cnt[BD * NN];
__device__ float g_dinv[BD * NN];

// ---------------- init: pos=points, vel=0, write t=0 output ----------------
__global__ void k_init(const float* __restrict__ pts, float* __restrict__ out) {
    int id = blockIdx.x * blockDim.x + threadIdx.x;   // over B*N*3
    if (id < BD * NN * 3) {
        float v = pts[id];
        g_pos[id] = v;
        g_vel[id] = 0.f;
        int c = id % 3;
        int n = (id / 3) % NN;
        int b = id / (3 * NN);
        out[((size_t)(b * (TT + 1)) * NN + n) * 3 + c] = v;
    }
}

// ---------------- adjacency: radius graph (self included, ascending j) -----
// grid (NN/64, BD), 256 threads. All batch positions cached in smem.
__global__ void k_adj(const float* __restrict__ padding) {
    __shared__ float px[NN], py[NN], pz[NN], pd[NN];
    int b = blockIdx.y;
    const float* pos = g_pos + (size_t)b * NN * 3;
    for (int j = threadIdx.x; j < NN; j += 256) {
        px[j] = pos[j * 3 + 0];
        py[j] = pos[j * 3 + 1];
        pz[j] = pos[j * 3 + 2];
        pd[j] = padding[b * NN + j];
    }
    __syncthreads();

    int warp = threadIdx.x >> 5, lane = threadIdx.x & 31;
    const float R2 = 0.01f;   // float32(0.1*0.1), matches fp32 compare in ref
    for (int r = 0; r < 8; r++) {
        int i = blockIdx.x * 64 + r * 8 + warp;
        float xi = px[i], yi = py[i], zi = pz[i];
        bool oki = pd[i] > 0.f;
        int base = (b * NN + i) * MAXN;
        int cnt = 0;
        #pragma unroll 4
        for (int t = 0; t < NN / 32; t++) {
            int j = t * 32 + lane;
            // separate mul/add rounding — matches XLA's sub/mul/reduce-add HLOs
            float dx = __fadd_rn(px[j], -xi);
            float dy = __fadd_rn(py[j], -yi);
            float dz = __fadd_rn(pz[j], -zi);
            float d2 = __fadd_rn(__fadd_rn(__fmul_rn(dx, dx), __fmul_rn(dy, dy)),
                                 __fmul_rn(dz, dz));
            // a_hat = adj + I: diagonal always 1; self included at sorted pos
            bool hit = (j == i) || (oki && (pd[j] > 0.f) && (d2 < R2));
            unsigned m = __ballot_sync(0xffffffffu, hit);
            if (hit) {
                int off = cnt + __popc(m & ((1u << lane) - 1u));
                if (off < MAXN) g_nbr[base + off] = j;
            }
            cnt += __popc(m);
        }
        if (cnt > MAXN) cnt = MAXN;
        if (lane == 0) {
            g_cnt[b * NN + i]  = cnt;
            // XLA lowers rsqrt as 1/sqrt (both correctly rounded), NOT the
            // 2-ulp MUFU.RSQ approximation that rsqrtf() compiles to.
            g_dinv[b * NN + i] = 1.0f / sqrtf((float)cnt);
        }
    }
}

// ---------------- layer0 h: h_j = (state_j @ W0) * dinv_j  (K=6) -----------
// grid (BD*NN/16), 128 threads: one output column per thread, 16 rows/block.
__global__ void k_l0h(const float* __restrict__ W0) {
    __shared__ float W0s[6 * HH];
    __shared__ float ss[16][6];
    __shared__ float dj[16];
    int row0 = blockIdx.x * 16;           // global row in [0, BD*NN)
    int tid = threadIdx.x;

    for (int k = tid; k < 6 * HH; k += 128) W0s[k] = W0[k];
    if (tid < 16 * 6) {
        int r = tid / 6, c = tid % 6;
        int g = row0 + r;
        ss[r][c] = (c < 3) ? g_pos[g * 3 + c] : g_vel[g * 3 + c - 3];
    }
    if (tid < 16) dj[tid] = g_dinv[row0 + tid];
    __syncthreads();

    int col = tid;
    for (int r = 0; r < 16; r++) {
        float acc = 0.f;
        #pragma unroll
        for (int k = 0; k < 6; k++) acc = fmaf(ss[r][k], W0s[k * HH + col], acc);
        g_h[(size_t)(row0 + r) * HH + col] = __fmul_rn(acc, dj[r]);
    }
}

// ---------------- dense GEMM: h_j = (x_j @ W) * dinv_j  (K=128) ------------
// src==0: read g_xa ; src==1: read g_xb.  Device symbols resolved in-kernel.
// Ascending-k single-accumulator FMA chain (matches Eigen/cutlass order).
// grid (BD*NN/64), 256 threads, dynamic smem.
__global__ void k_gemm(int src, const float* __restrict__ W) {
    extern __shared__ float sm[];
    float* Ws = sm;                 // 128*128
    float* xs = sm + HH * HH;       // 64*129 (padded)
    float* dj = xs + 64 * 129;      // 64

    const float* xin = src ? g_xb : g_xa;

    int row0 = blockIdx.x * 64;
    int tid = threadIdx.x;

    for (int k = tid; k < HH * HH; k += 256) Ws[k] = W[k];
    // load 64 input rows (each warp: 8 rows, 4 col chunks)
    {
        int warp = tid >> 5, lane = tid & 31;
        for (int r = warp; r < 64; r += 8) {
            const float* xr = xin + (size_t)(row0 + r) * HH;
            xs[r * 129 + lane]      = xr[lane];
            xs[r * 129 + lane + 32] = xr[lane + 32];
            xs[r * 129 + lane + 64] = xr[lane + 64];
            xs[r * 129 + lane + 96] = xr[lane + 96];
        }
        if (tid < 64) dj[tid] = g_dinv[row0 + tid];
    }
    __syncthreads();

    int tc = tid & 15, tr = tid >> 4;      // 16 col-groups x 16 row-groups
    float acc[4][8];
    #pragma unroll
    for (int m = 0; m < 4; m++)
        #pragma unroll
        for (int n = 0; n < 8; n++) acc[m][n] = 0.f;

    const float* yb = xs + (4 * tr) * 129;
    #pragma unroll 4
    for (int k = 0; k < HH; k++) {
        float yv[4] = {yb[k], yb[129 + k], yb[258 + k], yb[387 + k]};
        float4 w0 = *(const float4*)&Ws[k * HH + 8 * tc];
        float4 w1 = *(const float4*)&Ws[k * HH + 8 * tc + 4];
        float wv[8] = {w0.x, w0.y, w0.z, w0.w, w1.x, w1.y, w1.z, w1.w};
        #pragma unroll
        for (int m = 0; m < 4; m++)
            #pragma unroll
            for (int n = 0; n < 8; n++) acc[m][n] = fmaf(yv[m], wv[n], acc[m][n]);
    }

    #pragma unroll
    for (int m = 0; m < 4; m++) {
        int r = 4 * tr + m;
        float d = dj[r];
        float o[8];
        #pragma unroll
        for (int n = 0; n < 8; n++) o[n] = __fmul_rn(acc[m][n], d);
        float4* dst = (float4*)&g_h[(size_t)(row0 + r) * HH + 8 * tc];
        dst[0] = make_float4(o[0], o[1], o[2], o[3]);
        dst[1] = make_float4(o[4], o[5], o[6], o[7]);
    }
}

// ---------------- aggregate: x_i = relu((sum_{j in nbr_i} h_j)*dinv_i + b) -
// dst==0: write g_xa ; dst==1: write g_xb.
// One warp per row; neighbors summed in ascending j order.
__global__ void k_agg(int dstSel, const float* __restrict__ bias) {
    float* xout = dstSel ? g_xb : g_xa;
    int warp = threadIdx.x >> 5, lane = threadIdx.x & 31;
    int i = blockIdx.x * 8 + warp;           // global row in [0, BD*NN)
    int cnt = g_cnt[i];
    int base = i * MAXN;
    int bN = (i / NN) * NN;                  // neighbors are batch-local ids
    float a0 = 0.f, a1 = 0.f, a2 = 0.f, a3 = 0.f;
    for (int t = 0; t < cnt; t++) {
        int j = g_nbr[base + t];
        const float* hr = g_h + (size_t)(bN + j) * HH;
        a0 = __fadd_rn(a0, hr[lane]);
        a1 = __fadd_rn(a1, hr[lane + 32]);
        a2 = __fadd_rn(a2, hr[lane + 64]);
        a3 = __fadd_rn(a3, hr[lane + 96]);
    }
    float di = g_dinv[i];
    float* dst = xout + (size_t)i * HH;
    dst[lane]      = fmaxf(__fadd_rn(__fmul_rn(a0, di), bias[lane]),      0.f);
    dst[lane + 32] = fmaxf(__fadd_rn(__fmul_rn(a1, di), bias[lane + 32]), 0.f);
    dst[lane + 64] = fmaxf(__fadd_rn(__fmul_rn(a2, di), bias[lane + 64]), 0.f);
    dst[lane + 96] = fmaxf(__fadd_rn(__fmul_rn(a3, di), bias[lane + 96]), 0.f);
}

// ---------------- fc: res = x @ Wfc + bfc ; update pos/vel ; emit output ----
__global__ void k_fc(const float* __restrict__ Wfc, const float* __restrict__ bfc,
                     const float* __restrict__ padding, float* __restrict__ out,
                     int t) {
    int id = blockIdx.x * blockDim.x + threadIdx.x;   // over B*N*6
    if (id >= BD * NN * 6) return;
    int c = id % 6;
    int i = (id / 6) % NN;
    int b = id / (6 * NN);
    const float* xr = g_xa + (size_t)(b * NN + i) * HH;   // layer2 output
    float acc = 0.f;
    #pragma unroll 8
    for (int k = 0; k < HH; k++) acc = fmaf(xr[k], Wfc[k * 6 + c], acc);
    float res = __fadd_rn(acc, bfc[c]);
    res = __fmul_rn(res, padding[b * NN + i]);
    if (c < 3) {
        float p = __fadd_rn(g_pos[(b * NN + i) * 3 + c], res);
        g_pos[(b * NN + i) * 3 + c] = p;
        out[((size_t)(b * (TT + 1) + t + 1) * NN + i) * 3 + c] = p;
    } else {
        int a = (b * NN + i) * 3 + (c - 3);
        g_vel[a] = __fadd_rn(g_vel[a], res);
    }
}

// ---------------- launch ----------------
extern "C" void kernel_launch(void* const* d_in, const int* in_sizes, int n_in,
                              void* d_out, int out_size) {
    const float* points  = (const float*)d_in[0];
    const float* padding = (const float*)d_in[5];
    const float* W0  = (const float*)d_in[6];
    const float* b0  = (const float*)d_in[7];
    const float* W1  = (const float*)d_in[8];
    const float* b1  = (const float*)d_in[9];
    const float* W2  = (const float*)d_in[10];
    const float* b2  = (const float*)d_in[11];
    const float* Wfc = (const float*)d_in[12];
    const float* bfc = (const float*)d_in[13];
    float* out = (float*)d_out;

    const int smem_gemm = (HH * HH + 64 * 129 + 64) * (int)sizeof(float);
    cudaFuncSetAttribute(k_gemm, cudaFuncAttributeMaxDynamicSharedMemorySize,
                         smem_gemm);

    const int ROWS = BD * NN;

    k_init<<<(BD * NN * 3 + 255) / 256, 256>>>(points, out);

    for (int t = 0; t < TT; t++) {
        k_adj<<<dim3(NN / 64, BD), 256>>>(padding);
        // layer 0: state -> h -> xa
        k_l0h<<<ROWS / 16, 128>>>(W0);
        k_agg<<<ROWS / 8, 256>>>(0, b0);                  // -> g_xa
        // layer 1: xa -> h -> xb
        k_gemm<<<ROWS / 64, 256, smem_gemm>>>(0, W1);     // read g_xa
        k_agg<<<ROWS / 8, 256>>>(1, b1);                  // -> g_xb
        // layer 2: xb -> h -> xa
        k_gemm<<<ROWS / 64, 256, smem_gemm>>>(1, W2);     // read g_xb
        k_agg<<<ROWS / 8, 256>>>(0, b2);                  // -> g_xa
        // fc + state update + output
        k_fc<<<(BD * NN * 6 + 255) / 256, 256>>>(Wfc, bfc, padding, out, t);
    }
}

// round 6
// speedup vs baseline: 1.6182x; 1.6182x over previous
#include <cuda_runtime.h>

// Problem constants (from reference setup_inputs)
#define BD   8        // batch
#define NN   2048     // N = O*K
#define HH   128      // hidden
#define TT   10       // pred_len
#define MAXN 256      // neighbor cap (avg degree ~10)

// ---------------- device scratch (no allocations allowed) ----------------
__device__ float g_pos[BD * NN * 3];
__device__ float g_vel[BD * NN * 3];
__device__ float g_ha[BD * NN * HH];     // h ping
__device__ float g_hb[BD * NN * HH];     // h pong
__device__ int   g_nbr[BD * NN * MAXN];
__device__ int   g_cnt[BD * NN];
__device__ float g_dinv[BD * NN];

// ---------------- init: pos=points, vel=0, write t=0 output ----------------
__global__ void k_init(const float* __restrict__ pts, float* __restrict__ out) {
    int id = blockIdx.x * blockDim.x + threadIdx.x;   // over B*N*3
    if (id < BD * NN * 3) {
        float v = pts[id];
        g_pos[id] = v;
        g_vel[id] = 0.f;
        int c = id % 3;
        int n = (id / 3) % NN;
        int b = id / (3 * NN);
        out[((size_t)(b * (TT + 1)) * NN + n) * 3 + c] = v;
    }
}

// ---------------- adjacency + fused layer0 h --------------------------------
// grid (NN/64, BD), 256 threads.
// Phase 1: radius scan for the block's 64 rows (self included, ascending j),
//          writes g_nbr/g_cnt/g_dinv.
// Phase 2: h_j = (state_j @ W0) * dinv_j for the same 64 rows -> g_ha.
__global__ __launch_bounds__(256) void k_adj(const float* __restrict__ padding,
                                             const float* __restrict__ W0) {
    __shared__ float px[NN], py[NN], pz[NN], pd[NN];
    __shared__ float W0s[6 * HH];
    __shared__ float sv[64][3];
    __shared__ float sdinv[64];
    int b = blockIdx.y, bN = b * NN;
    int i0 = blockIdx.x * 64;
    int tid = threadIdx.x;
    const float* pos = g_pos + (size_t)bN * 3;
    for (int j = tid; j < NN; j += 256) {
        px[j] = pos[j * 3 + 0];
        py[j] = pos[j * 3 + 1];
        pz[j] = pos[j * 3 + 2];
        pd[j] = padding[bN + j];
    }
    for (int k = tid; k < 6 * HH; k += 256) W0s[k] = W0[k];
    if (tid < 192) sv[tid / 3][tid % 3] = g_vel[(bN + i0 + tid / 3) * 3 + tid % 3];
    __syncthreads();

    int warp = tid >> 5, lane = tid & 31;
    const float R2 = 0.01f;   // float32(0.1*0.1), fp32 compare like the ref
    for (int r = 0; r < 8; r++) {
        int rr = r * 8 + warp;            // row-in-block 0..63
        int i = i0 + rr;
        float xi = px[i], yi = py[i], zi = pz[i];
        bool oki = pd[i] > 0.f;
        int base = (bN + i) * MAXN;
        int cnt = 0;
        #pragma unroll 4
        for (int t = 0; t < NN / 32; t++) {
            int j = t * 32 + lane;
            // separate mul/add rounding — matches XLA's sub/mul/reduce-add
            float dx = __fadd_rn(px[j], -xi);
            float dy = __fadd_rn(py[j], -yi);
            float dz = __fadd_rn(pz[j], -zi);
            float d2 = __fadd_rn(__fadd_rn(__fmul_rn(dx, dx), __fmul_rn(dy, dy)),
                                 __fmul_rn(dz, dz));
            // a_hat = adj + I: diagonal always 1; self at its sorted position
            bool hit = (j == i) || (oki && (pd[j] > 0.f) && (d2 < R2));
            unsigned m = __ballot_sync(0xffffffffu, hit);
            if (hit) {
                int off = cnt + __popc(m & ((1u << lane) - 1u));
                if (off < MAXN) g_nbr[base + off] = j;
            }
            cnt += __popc(m);
        }
        if (cnt > MAXN) cnt = MAXN;
        if (lane == 0) {
            // XLA lowers rsqrt as 1/sqrt (correctly rounded), NOT MUFU.RSQ.
            float di = 1.0f / sqrtf((float)cnt);
            g_cnt[bN + i]  = cnt;
            g_dinv[bN + i] = di;
            sdinv[rr] = di;
        }
    }
    __syncthreads();

    // layer0 h for own rows (ascending-k FMA, pos then vel — same as before)
    for (int o = tid; o < 64 * HH; o += 256) {
        int r = o >> 7, col = o & 127;
        float acc = 0.f;
        acc = fmaf(px[i0 + r], W0s[0 * HH + col], acc);
        acc = fmaf(py[i0 + r], W0s[1 * HH + col], acc);
        acc = fmaf(pz[i0 + r], W0s[2 * HH + col], acc);
        acc = fmaf(sv[r][0],   W0s[3 * HH + col], acc);
        acc = fmaf(sv[r][1],   W0s[4 * HH + col], acc);
        acc = fmaf(sv[r][2],   W0s[5 * HH + col], acc);
        g_ha[(size_t)(bN + i0 + r) * HH + col] = __fmul_rn(acc, sdinv[r]);
    }
}

// ---------------- fused aggregate + dense GEMM ------------------------------
// Phase A: x_i = relu((sum_{j in nbr_i} h_j)*dinv_i + bias)  -> smem xs
// Phase B: h'_i = (x_i @ W) * dinv_i                          -> other h buf
// src==0: g_ha -> g_hb ; src==1: g_hb -> g_ha.
// grid (BD*NN/64), 256 threads, dynamic smem.
__global__ __launch_bounds__(256) void k_aggemm(int src,
                                                const float* __restrict__ bias,
                                                const float* __restrict__ W) {
    extern __shared__ float sm[];
    float* Ws = sm;                 // 128*128
    float* xs = sm + HH * HH;       // 64*129 (padded)
    float* dj = xs + 64 * 129;      // 64
    float* bs = dj + 64;            // 128

    const float* hin  = src ? g_hb : g_ha;
    float*       hout = src ? g_ha : g_hb;

    int row0 = blockIdx.x * 64;
    int tid = threadIdx.x;
    int bN = (row0 / NN) * NN;      // neighbors are batch-local ids

    for (int k = tid; k < HH * HH; k += 256) Ws[k] = W[k];
    if (tid < HH) bs[tid] = bias[tid];
    if (tid < 64) dj[tid] = g_dinv[row0 + tid];
    __syncthreads();

    // Phase A: one warp per row, neighbors summed in ascending j order
    int warp = tid >> 5, lane = tid & 31;
    for (int r = warp; r < 64; r += 8) {
        int i = row0 + r;
        int cnt = g_cnt[i];
        const int* nb = g_nbr + (size_t)i * MAXN;
        float a0 = 0.f, a1 = 0.f, a2 = 0.f, a3 = 0.f;
        for (int t = 0; t < cnt; t++) {
            const float* hr = hin + (size_t)(bN + nb[t]) * HH;
            a0 = __fadd_rn(a0, hr[lane]);
            a1 = __fadd_rn(a1, hr[lane + 32]);
            a2 = __fadd_rn(a2, hr[lane + 64]);
            a3 = __fadd_rn(a3, hr[lane + 96]);
        }
        float di = dj[r];
        xs[r * 129 + lane]      = fmaxf(__fadd_rn(__fmul_rn(a0, di), bs[lane]),      0.f);
        xs[r * 129 + lane + 32] = fmaxf(__fadd_rn(__fmul_rn(a1, di), bs[lane + 32]), 0.f);
        xs[r * 129 + lane + 64] = fmaxf(__fadd_rn(__fmul_rn(a2, di), bs[lane + 64]), 0.f);
        xs[r * 129 + lane + 96] = fmaxf(__fadd_rn(__fmul_rn(a3, di), bs[lane + 96]), 0.f);
    }
    __syncthreads();

    // Phase B: xs(64x128) @ Ws(128x128), ascending-k single-accumulator FMA
    int tc = tid & 15, tr = tid >> 4;      // 16 col-groups x 16 row-groups
    float acc[4][8];
    #pragma unroll
    for (int m = 0; m < 4; m++)
        #pragma unroll
        for (int n = 0; n < 8; n++) acc[m][n] = 0.f;

    const float* yb = xs + (4 * tr) * 129;
    #pragma unroll 4
    for (int k = 0; k < HH; k++) {
        float yv[4] = {yb[k], yb[129 + k], yb[258 + k], yb[387 + k]};
        float4 w0 = *(const float4*)&Ws[k * HH + 8 * tc];
        float4 w1 = *(const float4*)&Ws[k * HH + 8 * tc + 4];
        float wv[8] = {w0.x, w0.y, w0.z, w0.w, w1.x, w1.y, w1.z, w1.w};
        #pragma unroll
        for (int m = 0; m < 4; m++)
            #pragma unroll
            for (int n = 0; n < 8; n++) acc[m][n] = fmaf(yv[m], wv[n], acc[m][n]);
    }

    #pragma unroll
    for (int m = 0; m < 4; m++) {
        int r = 4 * tr + m;
        float d = dj[r];
        float o[8];
        #pragma unroll
        for (int n = 0; n < 8; n++) o[n] = __fmul_rn(acc[m][n], d);
        float4* dst = (float4*)&hout[(size_t)(row0 + r) * HH + 8 * tc];
        dst[0] = make_float4(o[0], o[1], o[2], o[3]);
        dst[1] = make_float4(o[4], o[5], o[6], o[7]);
    }
}

// ---------------- fused aggregate + fc head + state update ------------------
// Phase A: x_i = relu((sum h_j)*dinv_i + b2) -> smem
// Phase B: res = x @ Wfc + bfc ; *pad ; pos/vel update ; emit output slice.
// Reads g_ha (layer2 gemm output lands there).
__global__ __launch_bounds__(256) void k_aggfc(const float* __restrict__ bias2,
                                               const float* __restrict__ Wfc,
                                               const float* __restrict__ bfc,
                                               const float* __restrict__ padding,
                                               float* __restrict__ out, int t) {
    __shared__ float xs[64 * 129];
    __shared__ float Wf[HH * 6];
    __shared__ float bf[6];
    int row0 = blockIdx.x * 64;
    int tid = threadIdx.x;
    int bN = (row0 / NN) * NN;

    for (int k = tid; k < HH * 6; k += 256) Wf[k] = Wfc[k];
    if (tid < 6) bf[tid] = bfc[tid];

    int warp = tid >> 5, lane = tid & 31;
    for (int r = warp; r < 64; r += 8) {
        int i = row0 + r;
        int cnt = g_cnt[i];
        const int* nb = g_nbr + (size_t)i * MAXN;
        float a0 = 0.f, a1 = 0.f, a2 = 0.f, a3 = 0.f;
        for (int tt = 0; tt < cnt; tt++) {
            const float* hr = g_ha + (size_t)(bN + nb[tt]) * HH;
            a0 = __fadd_rn(a0, hr[lane]);
            a1 = __fadd_rn(a1, hr[lane + 32]);
            a2 = __fadd_rn(a2, hr[lane + 64]);
            a3 = __fadd_rn(a3, hr[lane + 96]);
        }
        float di = g_dinv[i];
        xs[r * 129 + lane]      = fmaxf(__fadd_rn(__fmul_rn(a0, di), bias2[lane]),      0.f);
        xs[r * 129 + lane + 32] = fmaxf(__fadd_rn(__fmul_rn(a1, di), bias2[lane + 32]), 0.f);
        xs[r * 129 + lane + 64] = fmaxf(__fadd_rn(__fmul_rn(a2, di), bias2[lane + 64]), 0.f);
        xs[r * 129 + lane + 96] = fmaxf(__fadd_rn(__fmul_rn(a3, di), bias2[lane + 96]), 0.f);
    }
    __syncthreads();

    for (int w = tid; w < 64 * 6; w += 256) {
        int r = w / 6, c = w % 6;
        int g = row0 + r;
        const float* xr = xs + r * 129;
        float acc = 0.f;
        #pragma unroll 8
        for (int k = 0; k < HH; k++) acc = fmaf(xr[k], Wf[k * 6 + c], acc);
        float res = __fadd_rn(acc, bf[c]);
        res = __fmul_rn(res, padding[g]);
        if (c < 3) {
            float p = __fadd_rn(g_pos[g * 3 + c], res);
            g_pos[g * 3 + c] = p;
            int b = g / NN, n = g % NN;
            out[((size_t)(b * (TT + 1) + t + 1) * NN + n) * 3 + c] = p;
        } else {
            int a = g * 3 + (c - 3);
            g_vel[a] = __fadd_rn(g_vel[a], res);
        }
    }
}

// ---------------- launch ----------------
extern "C" void kernel_launch(void* const* d_in, const int* in_sizes, int n_in,
                              void* d_out, int out_size) {
    const float* points  = (const float*)d_in[0];
    const float* padding = (const float*)d_in[5];
    const float* W0  = (const float*)d_in[6];
    const float* b0  = (const float*)d_in[7];
    const float* W1  = (const float*)d_in[8];
    const float* b1  = (const float*)d_in[9];
    const float* W2  = (const float*)d_in[10];
    const float* b2  = (const float*)d_in[11];
    const float* Wfc = (const float*)d_in[12];
    const float* bfc = (const float*)d_in[13];
    float* out = (float*)d_out;

    const int smem_ag = (HH * HH + 64 * 129 + 64 + HH) * (int)sizeof(float);
    cudaFuncSetAttribute(k_aggemm, cudaFuncAttributeMaxDynamicSharedMemorySize,
                         smem_ag);

    const int ROWS = BD * NN;

    k_init<<<(BD * NN * 3 + 255) / 256, 256>>>(points, out);

    for (int t = 0; t < TT; t++) {
        k_adj<<<dim3(NN / 64, BD), 256>>>(padding, W0);          // -> g_ha (h0)
        k_aggemm<<<ROWS / 64, 256, smem_ag>>>(0, b0, W1);        // ha -> x -> hb
        k_aggemm<<<ROWS / 64, 256, smem_ag>>>(1, b1, W2);        // hb -> x -> ha
        k_aggfc <<<ROWS / 64, 256>>>(b2, Wfc, bfc, padding, out, t);
    }
}